// round 8
// baseline (speedup 1.0000x reference)
#include <cuda_runtime.h>
#include <cuda_bf16.h>
#include <cstdint>

#define N_NODES 100000
#define N_EDGES 600000
#define HID 128
#define OUT 24

// ---------------- scratch ----------------
__device__ float g_h  [(size_t)N_NODES * HID];
__device__ float g_agg[(size_t)N_NODES * HID];
__device__ float g_hid[(size_t)N_NODES * HID];

// ---------------- helpers ----------------
__device__ __forceinline__ unsigned long long pk2(float lo, float hi) {
    unsigned long long r;
    asm("mov.b64 %0, {%1, %2};" : "=l"(r) : "f"(lo), "f"(hi));
    return r;
}
__device__ __forceinline__ void fma2(unsigned long long& d,
                                     unsigned long long a, unsigned long long b) {
    asm("fma.rn.f32x2 %0, %1, %2, %0;" : "+l"(d) : "l"(a), "l"(b));
}
__device__ __forceinline__ float2 upk(unsigned long long v) {
    float2 f;
    asm("mov.b64 {%0, %1}, %2;" : "=f"(f.x), "=f"(f.y) : "l"(v));
    return f;
}
__device__ __forceinline__ uint32_t f2tf32(float f) {
    uint32_t u;
    asm("cvt.rna.tf32.f32 %0, %1;" : "=r"(u) : "f"(f));
    return u;
}
__device__ __forceinline__ void red_add_v2(float* addr, float x, float y) {
    asm volatile("red.global.add.v2.f32 [%0], {%1, %2};"
                 :: "l"(addr), "f"(x), "f"(y) : "memory");
}
__device__ __forceinline__ void mma_tf32(float* c, const uint32_t* a,
                                         uint32_t b0, uint32_t b1) {
    asm volatile(
        "mma.sync.aligned.m16n8k8.row.col.f32.tf32.tf32.f32 "
        "{%0,%1,%2,%3}, {%4,%5,%6,%7}, {%8,%9}, {%0,%1,%2,%3};"
        : "+f"(c[0]), "+f"(c[1]), "+f"(c[2]), "+f"(c[3])
        : "r"(a[0]), "r"(a[1]), "r"(a[2]), "r"(a[3]), "r"(b0), "r"(b1));
}

// ---------------- tf32 tensor-core GEMM (exact R7) -------------------------
#define BM 128
#define BN 128
#define BK 16
#define APAD 136

template<bool RELU>
__global__ __launch_bounds__(256)
void tgemm_kernel(const float* __restrict__ A, int lda,
                  const float* __restrict__ W, int ldw,
                  const float* __restrict__ bias,
                  float* __restrict__ C, int ldc,
                  int M, int K)
{
    __shared__ uint32_t As[BK][APAD];
    __shared__ uint32_t Ws[BK][APAD];

    const int tid  = threadIdx.x;
    const int m0   = blockIdx.y * BM;
    const int warp = tid >> 5;
    const int lane = tid & 31;
    const int g    = lane >> 2;
    const int tig  = lane & 3;
    const int wm   = (warp & 3) * 32;
    const int wn   = (warp >> 2) * 64;

    float acc[2][8][4];
    #pragma unroll
    for (int i = 0; i < 2; i++)
        #pragma unroll
        for (int j = 0; j < 8; j++)
            #pragma unroll
            for (int q = 0; q < 4; q++) acc[i][j][q] = 0.f;

    for (int k0 = 0; k0 < K; k0 += BK) {
        #pragma unroll
        for (int p = 0; p < 2; p++) {
            int idx = tid + p * 256;
            int m   = idx >> 2;
            int k4  = (idx & 3) << 2;
            float4 v = make_float4(0.f, 0.f, 0.f, 0.f);
            int gm = m0 + m;
            if (gm < M)
                v = *reinterpret_cast<const float4*>(A + (size_t)gm * lda + k0 + k4);
            As[k4 + 0][m] = f2tf32(v.x);
            As[k4 + 1][m] = f2tf32(v.y);
            As[k4 + 2][m] = f2tf32(v.z);
            As[k4 + 3][m] = f2tf32(v.w);
        }
        #pragma unroll
        for (int p = 0; p < 2; p++) {
            int idx = tid + p * 256;
            int k   = idx >> 5;
            int n4  = (idx & 31) << 2;
            float4 v = *reinterpret_cast<const float4*>(W + (size_t)(k0 + k) * ldw + n4);
            Ws[k][n4 + 0] = f2tf32(v.x);
            Ws[k][n4 + 1] = f2tf32(v.y);
            Ws[k][n4 + 2] = f2tf32(v.z);
            Ws[k][n4 + 3] = f2tf32(v.w);
        }
        __syncthreads();

        #pragma unroll
        for (int kk = 0; kk < BK; kk += 8) {
            uint32_t a[2][4];
            #pragma unroll
            for (int mf = 0; mf < 2; mf++) {
                a[mf][0] = As[kk + tig    ][wm + mf * 16 + g];
                a[mf][1] = As[kk + tig    ][wm + mf * 16 + g + 8];
                a[mf][2] = As[kk + tig + 4][wm + mf * 16 + g];
                a[mf][3] = As[kk + tig + 4][wm + mf * 16 + g + 8];
            }
            #pragma unroll
            for (int nf = 0; nf < 8; nf++) {
                uint32_t b0 = Ws[kk + tig    ][wn + nf * 8 + g];
                uint32_t b1 = Ws[kk + tig + 4][wn + nf * 8 + g];
                #pragma unroll
                for (int mf = 0; mf < 2; mf++)
                    mma_tf32(acc[mf][nf], a[mf], b0, b1);
            }
        }
        __syncthreads();
    }

    #pragma unroll
    for (int mf = 0; mf < 2; mf++) {
        int r0 = m0 + wm + mf * 16 + g;
        #pragma unroll
        for (int nf = 0; nf < 8; nf++) {
            int col = wn + nf * 8 + 2 * tig;
            float bv0 = bias ? bias[col]     : 0.f;
            float bv1 = bias ? bias[col + 1] : 0.f;
            float c0 = acc[mf][nf][0] + bv0, c1 = acc[mf][nf][1] + bv1;
            float c2 = acc[mf][nf][2] + bv0, c3 = acc[mf][nf][3] + bv1;
            if (RELU) {
                c0 = fmaxf(c0, 0.f); c1 = fmaxf(c1, 0.f);
                c2 = fmaxf(c2, 0.f); c3 = fmaxf(c3, 0.f);
            }
            if (r0 < M)
                *reinterpret_cast<float2*>(C + (size_t)r0 * ldc + col) = make_float2(c0, c1);
            if (r0 + 8 < M)
                *reinterpret_cast<float2*>(C + (size_t)(r0 + 8) * ldc + col) = make_float2(c2, c3);
        }
    }
}

// ---------------- copy kernel ----------------
__global__ void copy_kernel(float4* __restrict__ dst, const float4* __restrict__ src, int n4)
{
    int i = blockIdx.x * blockDim.x + threadIdx.x;
    if (i < n4) dst[i] = src[i];
}

// ---------------- tensor-core edge scatter ---------------------------------
// 256 threads, 64 edges/block. e_emb tile [64x128] = ea[64x32] @ ew[32x128]
// via mma.sync; epilogue: relu(e_emb + eb + h[src]) -> red.add.v2 into agg[dst].
#define SE 64

__global__ __launch_bounds__(256)
void edge_scatter_tc(const float* __restrict__ h,
                     const int* __restrict__ src,
                     const int* __restrict__ dst,
                     const float* __restrict__ ea,
                     const float* __restrict__ ew,
                     const float* __restrict__ eb,
                     float* __restrict__ agg,
                     int E)
{
    __shared__ uint32_t ea_s[32][SE + 8];   // [k][e]
    __shared__ uint32_t ew_s[32][136];      // [k][n]
    __shared__ int src_s[SE];
    __shared__ int dst_s[SE];

    const int tid  = threadIdx.x;
    const int warp = tid >> 5;
    const int lane = tid & 31;
    const int g    = lane >> 2;
    const int tig  = lane & 3;
    const int wn   = warp * 16;

    const int base = blockIdx.x * SE;
    const int ne = min(SE, E - base);
    if (ne <= 0) return;

    for (int idx = tid; idx < 32 * HID; idx += 256)
        ew_s[idx >> 7][idx & 127] = f2tf32(ew[idx]);
    for (int idx = tid; idx < SE * 32; idx += 256) {
        int e = idx >> 5, k = idx & 31;
        float v = (e < ne) ? ea[(size_t)(base + e) * 32 + k] : 0.f;
        ea_s[k][e] = f2tf32(v);
    }
    if (tid < ne) {
        src_s[tid] = src[base + tid];
        dst_s[tid] = dst[base + tid];
    }
    __syncthreads();

    float acc[4][2][4];
    #pragma unroll
    for (int mf = 0; mf < 4; mf++)
        #pragma unroll
        for (int nf = 0; nf < 2; nf++)
            #pragma unroll
            for (int q = 0; q < 4; q++) acc[mf][nf][q] = 0.f;

    #pragma unroll
    for (int kk = 0; kk < 32; kk += 8) {
        uint32_t a[4][4];
        #pragma unroll
        for (int mf = 0; mf < 4; mf++) {
            a[mf][0] = ea_s[kk + tig    ][mf * 16 + g];
            a[mf][1] = ea_s[kk + tig    ][mf * 16 + g + 8];
            a[mf][2] = ea_s[kk + tig + 4][mf * 16 + g];
            a[mf][3] = ea_s[kk + tig + 4][mf * 16 + g + 8];
        }
        #pragma unroll
        for (int nf = 0; nf < 2; nf++) {
            uint32_t b0 = ew_s[kk + tig    ][wn + nf * 8 + g];
            uint32_t b1 = ew_s[kk + tig + 4][wn + nf * 8 + g];
            #pragma unroll
            for (int mf = 0; mf < 4; mf++)
                mma_tf32(acc[mf][nf], a[mf], b0, b1);
        }
    }

    const int col0 = wn + 2 * tig;
    const float2 eb0 = *reinterpret_cast<const float2*>(eb + col0);
    const float2 eb1 = *reinterpret_cast<const float2*>(eb + col0 + 8);

    #pragma unroll
    for (int mf = 0; mf < 4; mf++) {
        int r = mf * 16 + g;
        if (r < ne) {
            int s = src_s[r], dd = dst_s[r];
            const float* hp = h + (size_t)s * HID;
            float* ap = agg + (size_t)dd * HID;
            float2 h0 = *reinterpret_cast<const float2*>(hp + col0);
            float2 h1 = *reinterpret_cast<const float2*>(hp + col0 + 8);
            red_add_v2(ap + col0,
                       fmaxf(acc[mf][0][0] + eb0.x + h0.x, 0.f),
                       fmaxf(acc[mf][0][1] + eb0.y + h0.y, 0.f));
            red_add_v2(ap + col0 + 8,
                       fmaxf(acc[mf][1][0] + eb1.x + h1.x, 0.f),
                       fmaxf(acc[mf][1][1] + eb1.y + h1.y, 0.f));
        }
        int r8 = r + 8;
        if (r8 < ne) {
            int s = src_s[r8], dd = dst_s[r8];
            const float* hp = h + (size_t)s * HID;
            float* ap = agg + (size_t)dd * HID;
            float2 h0 = *reinterpret_cast<const float2*>(hp + col0);
            float2 h1 = *reinterpret_cast<const float2*>(hp + col0 + 8);
            red_add_v2(ap + col0,
                       fmaxf(acc[mf][0][2] + eb0.x + h0.x, 0.f),
                       fmaxf(acc[mf][0][3] + eb0.y + h0.y, 0.f));
            red_add_v2(ap + col0 + 8,
                       fmaxf(acc[mf][1][2] + eb1.x + h1.x, 0.f),
                       fmaxf(acc[mf][1][3] + eb1.y + h1.y, 0.f));
        }
    }
}

// ---------------- tensor-core classifier -----------------------------------
// Phase 1 (tc): hid[64x128] = relu(ea@w1c + b1 + P[src] + Q[dst])
// Phase 2 (FFMA2): out[64x24] = hid @ w2t^T + b2
// Dynamic smem, phase-union layout.
#define HS_OFF   0
#define HS_ROW   132
#define EA_OFF   33792              // 64*132*4
#define W1C_OFF  (EA_OFF + 9216)    // ea: 32*72*4
#define W2T_OFF  33792              // union with ea/w1c (phase 2)
#define W2T_ROW  132
#define IDX_OFF  60416              // after w1c end (43008+17408)
#define CLS_SMEM 60928

__global__ __launch_bounds__(256)
void cls_tc_kernel(const float* __restrict__ P,
                   const float* __restrict__ Q,
                   const int* __restrict__ src,
                   const int* __restrict__ dst,
                   const float* __restrict__ ea,
                   const float* __restrict__ w1c,  // [32,128]
                   const float* __restrict__ b1,   // [128]
                   const float* __restrict__ w2,   // [128,24]
                   const float* __restrict__ b2,   // [24]
                   float* __restrict__ out,        // [E,24]
                   int E)
{
    extern __shared__ char smem_raw[];
    float    (*hid_s)[HS_ROW] = reinterpret_cast<float(*)[HS_ROW]>(smem_raw + HS_OFF);
    uint32_t (*ea_s)[SE + 8]  = reinterpret_cast<uint32_t(*)[SE + 8]>(smem_raw + EA_OFF);
    uint32_t (*w1c_s)[136]    = reinterpret_cast<uint32_t(*)[136]>(smem_raw + W1C_OFF);
    float    (*w2t)[W2T_ROW]  = reinterpret_cast<float(*)[W2T_ROW]>(smem_raw + W2T_OFF);
    int* src_s = reinterpret_cast<int*>(smem_raw + IDX_OFF);
    int* dst_s = src_s + SE;

    const int tid  = threadIdx.x;
    const int warp = tid >> 5;
    const int lane = tid & 31;
    const int g    = lane >> 2;
    const int tig  = lane & 3;
    const int wn   = warp * 16;

    const int base = blockIdx.x * SE;
    const int ne = min(SE, E - base);
    if (ne <= 0) return;

    for (int idx = tid; idx < 32 * HID; idx += 256)
        w1c_s[idx >> 7][idx & 127] = f2tf32(w1c[idx]);
    for (int idx = tid; idx < SE * 32; idx += 256) {
        int e = idx >> 5, k = idx & 31;
        float v = (e < ne) ? ea[(size_t)(base + e) * 32 + k] : 0.f;
        ea_s[k][e] = f2tf32(v);
    }
    if (tid < ne) {
        src_s[tid] = src[base + tid];
        dst_s[tid] = dst[base + tid];
    }
    __syncthreads();

    float acc[4][2][4];
    #pragma unroll
    for (int mf = 0; mf < 4; mf++)
        #pragma unroll
        for (int nf = 0; nf < 2; nf++)
            #pragma unroll
            for (int q = 0; q < 4; q++) acc[mf][nf][q] = 0.f;

    #pragma unroll
    for (int kk = 0; kk < 32; kk += 8) {
        uint32_t a[4][4];
        #pragma unroll
        for (int mf = 0; mf < 4; mf++) {
            a[mf][0] = ea_s[kk + tig    ][mf * 16 + g];
            a[mf][1] = ea_s[kk + tig    ][mf * 16 + g + 8];
            a[mf][2] = ea_s[kk + tig + 4][mf * 16 + g];
            a[mf][3] = ea_s[kk + tig + 4][mf * 16 + g + 8];
        }
        #pragma unroll
        for (int nf = 0; nf < 2; nf++) {
            uint32_t b0 = w1c_s[kk + tig    ][wn + nf * 8 + g];
            uint32_t b1 = w1c_s[kk + tig + 4][wn + nf * 8 + g];
            #pragma unroll
            for (int mf = 0; mf < 4; mf++)
                mma_tf32(acc[mf][nf], a[mf], b0, b1);
        }
    }

    const int col0 = wn + 2 * tig;
    const float2 bb0 = *reinterpret_cast<const float2*>(b1 + col0);
    const float2 bb1 = *reinterpret_cast<const float2*>(b1 + col0 + 8);

    #pragma unroll
    for (int mf = 0; mf < 4; mf++) {
        int r = mf * 16 + g;
        if (r < ne) {
            int s = src_s[r], dd = dst_s[r];
            const float* pp = P + (size_t)s * HID;
            const float* qp = Q + (size_t)dd * HID;
            float2 p0 = *reinterpret_cast<const float2*>(pp + col0);
            float2 q0 = *reinterpret_cast<const float2*>(qp + col0);
            float2 p1 = *reinterpret_cast<const float2*>(pp + col0 + 8);
            float2 q1 = *reinterpret_cast<const float2*>(qp + col0 + 8);
            *reinterpret_cast<float2*>(&hid_s[r][col0]) = make_float2(
                fmaxf(acc[mf][0][0] + bb0.x + p0.x + q0.x, 0.f),
                fmaxf(acc[mf][0][1] + bb0.y + p0.y + q0.y, 0.f));
            *reinterpret_cast<float2*>(&hid_s[r][col0 + 8]) = make_float2(
                fmaxf(acc[mf][1][0] + bb1.x + p1.x + q1.x, 0.f),
                fmaxf(acc[mf][1][1] + bb1.y + p1.y + q1.y, 0.f));
        }
        int r8 = r + 8;
        if (r8 < ne) {
            int s = src_s[r8], dd = dst_s[r8];
            const float* pp = P + (size_t)s * HID;
            const float* qp = Q + (size_t)dd * HID;
            float2 p0 = *reinterpret_cast<const float2*>(pp + col0);
            float2 q0 = *reinterpret_cast<const float2*>(qp + col0);
            float2 p1 = *reinterpret_cast<const float2*>(pp + col0 + 8);
            float2 q1 = *reinterpret_cast<const float2*>(qp + col0 + 8);
            *reinterpret_cast<float2*>(&hid_s[r8][col0]) = make_float2(
                fmaxf(acc[mf][0][2] + bb0.x + p0.x + q0.x, 0.f),
                fmaxf(acc[mf][0][3] + bb0.y + p0.y + q0.y, 0.f));
            *reinterpret_cast<float2*>(&hid_s[r8][col0 + 8]) = make_float2(
                fmaxf(acc[mf][1][2] + bb1.x + p1.x + q1.x, 0.f),
                fmaxf(acc[mf][1][3] + bb1.y + p1.y + q1.y, 0.f));
        }
    }
    __syncthreads();

    // phase 2 setup: w2t overwrites ea/w1c region
    for (int idx = tid; idx < HID * OUT; idx += 256) {
        float v = w2[idx];
        w2t[idx % OUT][idx / OUT] = v;
    }
    __syncthreads();

    // phase 2: [64 x 24] = hid_s[64 x 128] @ w2t^T, 2 edges x 3 outs / thread
    const int oq = tid & 7;
    const int eq = tid >> 3;        // 0..31
    const int o0 = oq * 3;
    const int e0 = eq * 2;

    unsigned long long acc2[2][3];
    #pragma unroll
    for (int i = 0; i < 2; i++)
        #pragma unroll
        for (int j = 0; j < 3; j++) acc2[i][j] = 0ull;

    #pragma unroll 4
    for (int dch = 0; dch < HID; dch += 4) {
        unsigned long long h2[2][2], w2r[3][2];
        #pragma unroll
        for (int i = 0; i < 2; i++) {
            const unsigned long long* hp =
                reinterpret_cast<const unsigned long long*>(&hid_s[e0 + i][dch]);
            h2[i][0] = hp[0]; h2[i][1] = hp[1];
        }
        #pragma unroll
        for (int j = 0; j < 3; j++) {
            const unsigned long long* wp =
                reinterpret_cast<const unsigned long long*>(&w2t[o0 + j][dch]);
            w2r[j][0] = wp[0]; w2r[j][1] = wp[1];
        }
        #pragma unroll
        for (int i = 0; i < 2; i++)
            #pragma unroll
            for (int j = 0; j < 3; j++) {
                fma2(acc2[i][j], h2[i][0], w2r[j][0]);
                fma2(acc2[i][j], h2[i][1], w2r[j][1]);
            }
    }

    #pragma unroll
    for (int i = 0; i < 2; i++) {
        int e = e0 + i;
        if (e >= ne) continue;
        #pragma unroll
        for (int j = 0; j < 3; j++) {
            float2 s = upk(acc2[i][j]);
            out[(size_t)(base + e) * OUT + o0 + j] = s.x + s.y + b2[o0 + j];
        }
    }
}

// ---------------- host ----------------
extern "C" void kernel_launch(void* const* d_in, const int* in_sizes, int n_in,
                              void* d_out, int out_size)
{
    const float* x      = (const float*)d_in[0];
    const int*   eidx   = (const int*)  d_in[1];
    const float* ea     = (const float*)d_in[2];
    const float* lin1_w = (const float*)d_in[3];
    const float* lin1_b = (const float*)d_in[4];
    const float* cls_w1 = (const float*)d_in[23];
    const float* cls_b1 = (const float*)d_in[24];
    const float* cls_w2 = (const float*)d_in[25];
    const float* cls_b2 = (const float*)d_in[26];

    const int NN = in_sizes[0] / 64;
    const int E  = in_sizes[2] / 32;
    const int* src = eidx;
    const int* dst = eidx + E;

    float *h, *agg, *hid;
    cudaGetSymbolAddress((void**)&h,   g_h);
    cudaGetSymbolAddress((void**)&agg, g_agg);
    cudaGetSymbolAddress((void**)&hid, g_hid);

    static bool attr_set = false;
    if (!attr_set) {
        cudaFuncSetAttribute(cls_tc_kernel,
                             cudaFuncAttributeMaxDynamicSharedMemorySize, CLS_SMEM);
        attr_set = true;
    }

    const dim3 gnode(1, (unsigned)((NN + BM - 1) / BM));
    const int eblocks = (E + SE - 1) / SE;
    const int copy_n4 = (NN * HID) / 4;
    const int copy_blocks = (copy_n4 + 255) / 256;

    tgemm_kernel<false><<<gnode, 256>>>(x, 64, lin1_w, HID, lin1_b, h, HID, NN, 64);

    for (int c = 0; c < 3; c++) {
        const float* ew = (const float*)d_in[5 + 6 * c];
        const float* eb = (const float*)d_in[6 + 6 * c];
        const float* w1 = (const float*)d_in[7 + 6 * c];
        const float* b1 = (const float*)d_in[8 + 6 * c];
        const float* w2 = (const float*)d_in[9 + 6 * c];
        const float* b2 = (const float*)d_in[10 + 6 * c];

        copy_kernel<<<copy_blocks, 256>>>((float4*)agg, (const float4*)h, copy_n4);
        edge_scatter_tc<<<eblocks, 256>>>(h, src, dst, ea, ew, eb, agg, E);
        tgemm_kernel<true><<<gnode, 256>>>(agg, HID, w1, HID, b1, hid, HID, NN, HID);
        tgemm_kernel<true><<<gnode, 256>>>(hid, HID, w2, HID, b2, h, HID, NN, HID);
    }

    tgemm_kernel<false><<<gnode, 256>>>(h, HID, cls_w1, HID, nullptr, hid, HID, NN, HID);
    tgemm_kernel<false><<<gnode, 256>>>(h, HID, cls_w1 + 128 * HID, HID, nullptr, agg, HID, NN, HID);

    cls_tc_kernel<<<eblocks, 256, CLS_SMEM>>>(hid, agg, src, dst, ea,
                                              cls_w1 + 256 * HID, cls_b1,
                                              cls_w2, cls_b2, (float*)d_out, E);
}

// round 9
// speedup vs baseline: 1.0908x; 1.0908x over previous
#include <cuda_runtime.h>
#include <cuda_bf16.h>
#include <cstdint>

#define N_NODES 100000
#define N_EDGES 600000
#define HID 128
#define OUT 24

// ---------------- scratch ----------------
__device__ float g_h  [(size_t)N_NODES * HID];
__device__ float g_agg[(size_t)N_NODES * HID];
__device__ float g_hid[(size_t)N_NODES * HID];

// ---------------- helpers ----------------
__device__ __forceinline__ unsigned long long pk2(float lo, float hi) {
    unsigned long long r;
    asm("mov.b64 %0, {%1, %2};" : "=l"(r) : "f"(lo), "f"(hi));
    return r;
}
__device__ __forceinline__ void fma2(unsigned long long& d,
                                     unsigned long long a, unsigned long long b) {
    asm("fma.rn.f32x2 %0, %1, %2, %0;" : "+l"(d) : "l"(a), "l"(b));
}
__device__ __forceinline__ float2 upk(unsigned long long v) {
    float2 f;
    asm("mov.b64 {%0, %1}, %2;" : "=f"(f.x), "=f"(f.y) : "l"(v));
    return f;
}
__device__ __forceinline__ uint32_t f2tf32(float f) {
    uint32_t u;
    asm("cvt.rna.tf32.f32 %0, %1;" : "=r"(u) : "f"(f));
    return u;
}
__device__ __forceinline__ void red_add_v4(float* addr, float4 v) {
    asm volatile("red.global.add.v4.f32 [%0], {%1, %2, %3, %4};"
                 :: "l"(addr), "f"(v.x), "f"(v.y), "f"(v.z), "f"(v.w)
                 : "memory");
}
__device__ __forceinline__ void mma_tf32(float* c, const uint32_t* a,
                                         uint32_t b0, uint32_t b1) {
    asm volatile(
        "mma.sync.aligned.m16n8k8.row.col.f32.tf32.tf32.f32 "
        "{%0,%1,%2,%3}, {%4,%5,%6,%7}, {%8,%9}, {%0,%1,%2,%3};"
        : "+f"(c[0]), "+f"(c[1]), "+f"(c[2]), "+f"(c[3])
        : "r"(a[0]), "r"(a[1]), "r"(a[2]), "r"(a[3]), "r"(b0), "r"(b1));
}

// ---------------- tf32 tensor-core GEMM (exact R7) -------------------------
#define BM 128
#define BN 128
#define BK 16
#define APAD 136

template<bool RELU>
__global__ __launch_bounds__(256)
void tgemm_kernel(const float* __restrict__ A, int lda,
                  const float* __restrict__ W, int ldw,
                  const float* __restrict__ bias,
                  float* __restrict__ C, int ldc,
                  int M, int K)
{
    __shared__ uint32_t As[BK][APAD];
    __shared__ uint32_t Ws[BK][APAD];

    const int tid  = threadIdx.x;
    const int m0   = blockIdx.y * BM;
    const int warp = tid >> 5;
    const int lane = tid & 31;
    const int g    = lane >> 2;
    const int tig  = lane & 3;
    const int wm   = (warp & 3) * 32;
    const int wn   = (warp >> 2) * 64;

    float acc[2][8][4];
    #pragma unroll
    for (int i = 0; i < 2; i++)
        #pragma unroll
        for (int j = 0; j < 8; j++)
            #pragma unroll
            for (int q = 0; q < 4; q++) acc[i][j][q] = 0.f;

    for (int k0 = 0; k0 < K; k0 += BK) {
        #pragma unroll
        for (int p = 0; p < 2; p++) {
            int idx = tid + p * 256;
            int m   = idx >> 2;
            int k4  = (idx & 3) << 2;
            float4 v = make_float4(0.f, 0.f, 0.f, 0.f);
            int gm = m0 + m;
            if (gm < M)
                v = *reinterpret_cast<const float4*>(A + (size_t)gm * lda + k0 + k4);
            As[k4 + 0][m] = f2tf32(v.x);
            As[k4 + 1][m] = f2tf32(v.y);
            As[k4 + 2][m] = f2tf32(v.z);
            As[k4 + 3][m] = f2tf32(v.w);
        }
        #pragma unroll
        for (int p = 0; p < 2; p++) {
            int idx = tid + p * 256;
            int k   = idx >> 5;
            int n4  = (idx & 31) << 2;
            float4 v = *reinterpret_cast<const float4*>(W + (size_t)(k0 + k) * ldw + n4);
            Ws[k][n4 + 0] = f2tf32(v.x);
            Ws[k][n4 + 1] = f2tf32(v.y);
            Ws[k][n4 + 2] = f2tf32(v.z);
            Ws[k][n4 + 3] = f2tf32(v.w);
        }
        __syncthreads();

        #pragma unroll
        for (int kk = 0; kk < BK; kk += 8) {
            uint32_t a[2][4];
            #pragma unroll
            for (int mf = 0; mf < 2; mf++) {
                a[mf][0] = As[kk + tig    ][wm + mf * 16 + g];
                a[mf][1] = As[kk + tig    ][wm + mf * 16 + g + 8];
                a[mf][2] = As[kk + tig + 4][wm + mf * 16 + g];
                a[mf][3] = As[kk + tig + 4][wm + mf * 16 + g + 8];
            }
            #pragma unroll
            for (int nf = 0; nf < 8; nf++) {
                uint32_t b0 = Ws[kk + tig    ][wn + nf * 8 + g];
                uint32_t b1 = Ws[kk + tig + 4][wn + nf * 8 + g];
                #pragma unroll
                for (int mf = 0; mf < 2; mf++)
                    mma_tf32(acc[mf][nf], a[mf], b0, b1);
            }
        }
        __syncthreads();
    }

    #pragma unroll
    for (int mf = 0; mf < 2; mf++) {
        int r0 = m0 + wm + mf * 16 + g;
        #pragma unroll
        for (int nf = 0; nf < 8; nf++) {
            int col = wn + nf * 8 + 2 * tig;
            float bv0 = bias ? bias[col]     : 0.f;
            float bv1 = bias ? bias[col + 1] : 0.f;
            float c0 = acc[mf][nf][0] + bv0, c1 = acc[mf][nf][1] + bv1;
            float c2 = acc[mf][nf][2] + bv0, c3 = acc[mf][nf][3] + bv1;
            if (RELU) {
                c0 = fmaxf(c0, 0.f); c1 = fmaxf(c1, 0.f);
                c2 = fmaxf(c2, 0.f); c3 = fmaxf(c3, 0.f);
            }
            if (r0 < M)
                *reinterpret_cast<float2*>(C + (size_t)r0 * ldc + col) = make_float2(c0, c1);
            if (r0 + 8 < M)
                *reinterpret_cast<float2*>(C + (size_t)(r0 + 8) * ldc + col) = make_float2(c2, c3);
        }
    }
}

// ---------------- copy kernel ----------------
__global__ void copy_kernel(float4* __restrict__ dst, const float4* __restrict__ src, int n4)
{
    int i = blockIdx.x * blockDim.x + threadIdx.x;
    if (i < n4) dst[i] = src[i];
}

// ---------------- TC edge scatter, coalesced row epilogue ------------------
// Phase 1: e_emb[64x128] = ea@ew + eb via mma.sync -> m_s (SMEM, row layout)
// Phase 2: warp per edge, lane owns a quad: v4 = relu(m_s + h[src]);
//          red.global.add.v4 into agg[dst]  (1 coalesced row read + 1 v4 red)
#define SE 64
#define MROW 132

__global__ __launch_bounds__(256)
void edge_scatter_tc(const float* __restrict__ h,
                     const int* __restrict__ src,
                     const int* __restrict__ dst,
                     const float* __restrict__ ea,
                     const float* __restrict__ ew,
                     const float* __restrict__ eb,
                     float* __restrict__ agg,
                     int E)
{
    __shared__ char pool[SE * MROW * 4 + 2 * SE * 4];
    uint32_t (*ea_s)[SE + 8] = reinterpret_cast<uint32_t(*)[SE + 8]>(pool);         // 9216B
    uint32_t (*ew_s)[136]    = reinterpret_cast<uint32_t(*)[136]>(pool + 9216);     // 17408B
    float    (*m_s)[MROW]    = reinterpret_cast<float(*)[MROW]>(pool);              // union, 33792B
    int* src_s = reinterpret_cast<int*>(pool + SE * MROW * 4);
    int* dst_s = src_s + SE;

    const int tid  = threadIdx.x;
    const int warp = tid >> 5;
    const int lane = tid & 31;
    const int g    = lane >> 2;
    const int tig  = lane & 3;
    const int wn   = warp * 16;

    const int base = blockIdx.x * SE;
    const int ne = min(SE, E - base);
    if (ne <= 0) return;

    for (int idx = tid; idx < 32 * HID; idx += 256)
        ew_s[idx >> 7][idx & 127] = f2tf32(ew[idx]);
    for (int idx = tid; idx < SE * 32; idx += 256) {
        int e = idx >> 5, k = idx & 31;
        float v = (e < ne) ? ea[(size_t)(base + e) * 32 + k] : 0.f;
        ea_s[k][e] = f2tf32(v);
    }
    if (tid < ne) {
        src_s[tid] = src[base + tid];
        dst_s[tid] = dst[base + tid];
    }
    __syncthreads();

    float acc[4][2][4];
    #pragma unroll
    for (int mf = 0; mf < 4; mf++)
        #pragma unroll
        for (int nf = 0; nf < 2; nf++)
            #pragma unroll
            for (int q = 0; q < 4; q++) acc[mf][nf][q] = 0.f;

    #pragma unroll
    for (int kk = 0; kk < 32; kk += 8) {
        uint32_t a[4][4];
        #pragma unroll
        for (int mf = 0; mf < 4; mf++) {
            a[mf][0] = ea_s[kk + tig    ][mf * 16 + g];
            a[mf][1] = ea_s[kk + tig    ][mf * 16 + g + 8];
            a[mf][2] = ea_s[kk + tig + 4][mf * 16 + g];
            a[mf][3] = ea_s[kk + tig + 4][mf * 16 + g + 8];
        }
        #pragma unroll
        for (int nf = 0; nf < 2; nf++) {
            uint32_t b0 = ew_s[kk + tig    ][wn + nf * 8 + g];
            uint32_t b1 = ew_s[kk + tig + 4][wn + nf * 8 + g];
            #pragma unroll
            for (int mf = 0; mf < 4; mf++)
                mma_tf32(acc[mf][nf], a[mf], b0, b1);
        }
    }

    const int col0 = wn + 2 * tig;
    const float2 eb0 = *reinterpret_cast<const float2*>(eb + col0);
    const float2 eb1 = *reinterpret_cast<const float2*>(eb + col0 + 8);
    __syncthreads();   // MMA fragment reads done; safe to clobber ea_s/ew_s with m_s

    #pragma unroll
    for (int mf = 0; mf < 4; mf++) {
        int r = mf * 16 + g;
        *reinterpret_cast<float2*>(&m_s[r][col0]) =
            make_float2(acc[mf][0][0] + eb0.x, acc[mf][0][1] + eb0.y);
        *reinterpret_cast<float2*>(&m_s[r][col0 + 8]) =
            make_float2(acc[mf][1][0] + eb1.x, acc[mf][1][1] + eb1.y);
        *reinterpret_cast<float2*>(&m_s[r + 8][col0]) =
            make_float2(acc[mf][0][2] + eb0.x, acc[mf][0][3] + eb0.y);
        *reinterpret_cast<float2*>(&m_s[r + 8][col0 + 8]) =
            make_float2(acc[mf][1][2] + eb1.x, acc[mf][1][3] + eb1.y);
    }
    __syncthreads();

    // phase 2: warp per edge, lane quad
    #pragma unroll
    for (int it = 0; it < SE / 8; it++) {
        int e = it * 8 + warp;
        if (e < ne) {
            int s = src_s[e], dd = dst_s[e];
            float4 m  = *reinterpret_cast<const float4*>(&m_s[e][lane * 4]);
            float4 hv = *reinterpret_cast<const float4*>(h + (size_t)s * HID + lane * 4);
            float4 v  = make_float4(fmaxf(m.x + hv.x, 0.f), fmaxf(m.y + hv.y, 0.f),
                                    fmaxf(m.z + hv.z, 0.f), fmaxf(m.w + hv.w, 0.f));
            red_add_v4(agg + (size_t)dd * HID + lane * 4, v);
        }
    }
}

// ---------------- TC classifier, coalesced row pass ------------------------
#define HS_OFF   0
#define HS_ROW   132
#define EA_OFF   33792
#define W1C_OFF  (EA_OFF + 9216)
#define W2T_OFF  33792
#define W2T_ROW  132
#define IDX_OFF  60416
#define CLS_SMEM 60928

__global__ __launch_bounds__(256)
void cls_tc_kernel(const float* __restrict__ P,
                   const float* __restrict__ Q,
                   const int* __restrict__ src,
                   const int* __restrict__ dst,
                   const float* __restrict__ ea,
                   const float* __restrict__ w1c,
                   const float* __restrict__ b1,
                   const float* __restrict__ w2,
                   const float* __restrict__ b2,
                   float* __restrict__ out,
                   int E)
{
    extern __shared__ char smem_raw[];
    float    (*hid_s)[HS_ROW] = reinterpret_cast<float(*)[HS_ROW]>(smem_raw + HS_OFF);
    uint32_t (*ea_s)[SE + 8]  = reinterpret_cast<uint32_t(*)[SE + 8]>(smem_raw + EA_OFF);
    uint32_t (*w1c_s)[136]    = reinterpret_cast<uint32_t(*)[136]>(smem_raw + W1C_OFF);
    float    (*w2t)[W2T_ROW]  = reinterpret_cast<float(*)[W2T_ROW]>(smem_raw + W2T_OFF);
    int* src_s = reinterpret_cast<int*>(smem_raw + IDX_OFF);
    int* dst_s = src_s + SE;

    const int tid  = threadIdx.x;
    const int warp = tid >> 5;
    const int lane = tid & 31;
    const int g    = lane >> 2;
    const int tig  = lane & 3;
    const int wn   = warp * 16;

    const int base = blockIdx.x * SE;
    const int ne = min(SE, E - base);
    if (ne <= 0) return;

    for (int idx = tid; idx < 32 * HID; idx += 256)
        w1c_s[idx >> 7][idx & 127] = f2tf32(w1c[idx]);
    for (int idx = tid; idx < SE * 32; idx += 256) {
        int e = idx >> 5, k = idx & 31;
        float v = (e < ne) ? ea[(size_t)(base + e) * 32 + k] : 0.f;
        ea_s[k][e] = f2tf32(v);
    }
    if (tid < ne) {
        src_s[tid] = src[base + tid];
        dst_s[tid] = dst[base + tid];
    }
    __syncthreads();

    float acc[4][2][4];
    #pragma unroll
    for (int mf = 0; mf < 4; mf++)
        #pragma unroll
        for (int nf = 0; nf < 2; nf++)
            #pragma unroll
            for (int q = 0; q < 4; q++) acc[mf][nf][q] = 0.f;

    #pragma unroll
    for (int kk = 0; kk < 32; kk += 8) {
        uint32_t a[4][4];
        #pragma unroll
        for (int mf = 0; mf < 4; mf++) {
            a[mf][0] = ea_s[kk + tig    ][mf * 16 + g];
            a[mf][1] = ea_s[kk + tig    ][mf * 16 + g + 8];
            a[mf][2] = ea_s[kk + tig + 4][mf * 16 + g];
            a[mf][3] = ea_s[kk + tig + 4][mf * 16 + g + 8];
        }
        #pragma unroll
        for (int nf = 0; nf < 2; nf++) {
            uint32_t b0 = w1c_s[kk + tig    ][wn + nf * 8 + g];
            uint32_t b1 = w1c_s[kk + tig + 4][wn + nf * 8 + g];
            #pragma unroll
            for (int mf = 0; mf < 4; mf++)
                mma_tf32(acc[mf][nf], a[mf], b0, b1);
        }
    }

    const int col0 = wn + 2 * tig;
    const float2 bb0 = *reinterpret_cast<const float2*>(b1 + col0);
    const float2 bb1 = *reinterpret_cast<const float2*>(b1 + col0 + 8);

    // store acc + b1 (no relu yet) into hid_s — hid_s region is separate
    #pragma unroll
    for (int mf = 0; mf < 4; mf++) {
        int r = mf * 16 + g;
        *reinterpret_cast<float2*>(&hid_s[r][col0]) =
            make_float2(acc[mf][0][0] + bb0.x, acc[mf][0][1] + bb0.y);
        *reinterpret_cast<float2*>(&hid_s[r][col0 + 8]) =
            make_float2(acc[mf][1][0] + bb1.x, acc[mf][1][1] + bb1.y);
        *reinterpret_cast<float2*>(&hid_s[r + 8][col0]) =
            make_float2(acc[mf][0][2] + bb0.x, acc[mf][0][3] + bb0.y);
        *reinterpret_cast<float2*>(&hid_s[r + 8][col0 + 8]) =
            make_float2(acc[mf][1][2] + bb1.x, acc[mf][1][3] + bb1.y);
    }
    __syncthreads();

    // coalesced row pass: warp per edge, lane quad: += P[src]+Q[dst], relu
    #pragma unroll
    for (int it = 0; it < SE / 8; it++) {
        int e = it * 8 + warp;
        if (e < ne) {
            int s = src_s[e], dd = dst_s[e];
            float4 hv = *reinterpret_cast<const float4*>(&hid_s[e][lane * 4]);
            float4 pv = *reinterpret_cast<const float4*>(P + (size_t)s * HID + lane * 4);
            float4 qv = *reinterpret_cast<const float4*>(Q + (size_t)dd * HID + lane * 4);
            hv.x = fmaxf(hv.x + pv.x + qv.x, 0.f);
            hv.y = fmaxf(hv.y + pv.y + qv.y, 0.f);
            hv.z = fmaxf(hv.z + pv.z + qv.z, 0.f);
            hv.w = fmaxf(hv.w + pv.w + qv.w, 0.f);
            *reinterpret_cast<float4*>(&hid_s[e][lane * 4]) = hv;
        }
    }
    __syncthreads();

    // phase 2 setup: w2t overwrites ea/w1c region
    for (int idx = tid; idx < HID * OUT; idx += 256) {
        float v = w2[idx];
        w2t[idx % OUT][idx / OUT] = v;
    }
    __syncthreads();

    const int oq = tid & 7;
    const int eq = tid >> 3;
    const int o0 = oq * 3;
    const int e0 = eq * 2;

    unsigned long long acc2[2][3];
    #pragma unroll
    for (int i = 0; i < 2; i++)
        #pragma unroll
        for (int j = 0; j < 3; j++) acc2[i][j] = 0ull;

    #pragma unroll 4
    for (int dch = 0; dch < HID; dch += 4) {
        unsigned long long h2[2][2], w2r[3][2];
        #pragma unroll
        for (int i = 0; i < 2; i++) {
            const unsigned long long* hp =
                reinterpret_cast<const unsigned long long*>(&hid_s[e0 + i][dch]);
            h2[i][0] = hp[0]; h2[i][1] = hp[1];
        }
        #pragma unroll
        for (int j = 0; j < 3; j++) {
            const unsigned long long* wp =
                reinterpret_cast<const unsigned long long*>(&w2t[o0 + j][dch]);
            w2r[j][0] = wp[0]; w2r[j][1] = wp[1];
        }
        #pragma unroll
        for (int i = 0; i < 2; i++)
            #pragma unroll
            for (int j = 0; j < 3; j++) {
                fma2(acc2[i][j], h2[i][0], w2r[j][0]);
                fma2(acc2[i][j], h2[i][1], w2r[j][1]);
            }
    }

    #pragma unroll
    for (int i = 0; i < 2; i++) {
        int e = e0 + i;
        if (e >= ne) continue;
        #pragma unroll
        for (int j = 0; j < 3; j++) {
            float2 s = upk(acc2[i][j]);
            out[(size_t)(base + e) * OUT + o0 + j] = s.x + s.y + b2[o0 + j];
        }
    }
}

// ---------------- host ----------------
extern "C" void kernel_launch(void* const* d_in, const int* in_sizes, int n_in,
                              void* d_out, int out_size)
{
    const float* x      = (const float*)d_in[0];
    const int*   eidx   = (const int*)  d_in[1];
    const float* ea     = (const float*)d_in[2];
    const float* lin1_w = (const float*)d_in[3];
    const float* lin1_b = (const float*)d_in[4];
    const float* cls_w1 = (const float*)d_in[23];
    const float* cls_b1 = (const float*)d_in[24];
    const float* cls_w2 = (const float*)d_in[25];
    const float* cls_b2 = (const float*)d_in[26];

    const int NN = in_sizes[0] / 64;
    const int E  = in_sizes[2] / 32;
    const int* src = eidx;
    const int* dst = eidx + E;

    float *h, *agg, *hid;
    cudaGetSymbolAddress((void**)&h,   g_h);
    cudaGetSymbolAddress((void**)&agg, g_agg);
    cudaGetSymbolAddress((void**)&hid, g_hid);

    static bool attr_set = false;
    if (!attr_set) {
        cudaFuncSetAttribute(cls_tc_kernel,
                             cudaFuncAttributeMaxDynamicSharedMemorySize, CLS_SMEM);
        attr_set = true;
    }

    const dim3 gnode(1, (unsigned)((NN + BM - 1) / BM));
    const int eblocks = (E + SE - 1) / SE;
    const int copy_n4 = (NN * HID) / 4;
    const int copy_blocks = (copy_n4 + 255) / 256;

    tgemm_kernel<false><<<gnode, 256>>>(x, 64, lin1_w, HID, lin1_b, h, HID, NN, 64);

    for (int c = 0; c < 3; c++) {
        const float* ew = (const float*)d_in[5 + 6 * c];
        const float* eb = (const float*)d_in[6 + 6 * c];
        const float* w1 = (const float*)d_in[7 + 6 * c];
        const float* b1 = (const float*)d_in[8 + 6 * c];
        const float* w2 = (const float*)d_in[9 + 6 * c];
        const float* b2 = (const float*)d_in[10 + 6 * c];

        copy_kernel<<<copy_blocks, 256>>>((float4*)agg, (const float4*)h, copy_n4);
        edge_scatter_tc<<<eblocks, 256>>>(h, src, dst, ea, ew, eb, agg, E);
        tgemm_kernel<true><<<gnode, 256>>>(agg, HID, w1, HID, b1, hid, HID, NN, HID);
        tgemm_kernel<true><<<gnode, 256>>>(hid, HID, w2, HID, b2, h, HID, NN, HID);
    }

    tgemm_kernel<false><<<gnode, 256>>>(h, HID, cls_w1, HID, nullptr, hid, HID, NN, HID);
    tgemm_kernel<false><<<gnode, 256>>>(h, HID, cls_w1 + 128 * HID, HID, nullptr, agg, HID, NN, HID);

    cls_tc_kernel<<<eblocks, 256, CLS_SMEM>>>(hid, agg, src, dst, ea,
                                              cls_w1 + 256 * HID, cls_b1,
                                              cls_w2, cls_b2, (float*)d_out, E);
}